// round 16
// baseline (speedup 1.0000x reference)
#include <cuda_runtime.h>
#include <cuda_bf16.h>
#include <math.h>
#include <stdint.h>

// Problem constants
#define NTOK   8192
#define DIN    1024
#define NT     12
#define NI     7
#define NL     8
#define NDEC   84
#define NOUT   96
#define DOUTD  1024
#define NHEADS 3

// ---------------- scratch (device globals) ----------------
__device__ __align__(16) float g_rt[NTOK * NOUT];            // routed, tf32-rounded fp32 [tok][96]
__device__ __align__(16) unsigned short g_whi[NOUT * DIN];   // W hi bf16 [96][1024]
__device__ __align__(16) unsigned short g_wlo[NOUT * DIN];   // W lo

__device__ __forceinline__ uint32_t smem_u32(const void* p) {
    uint32_t a;
    asm("{ .reg .u64 t; cvta.to.shared.u64 t, %1; cvt.u32.u64 %0, t; }" : "=r"(a) : "l"(p));
    return a;
}
__device__ __forceinline__ void split_bf16(float x, unsigned short &h, unsigned short &l) {
    __nv_bfloat16 hb = __float2bfloat16(x);
    float hf = __bfloat162float(hb);
    __nv_bfloat16 lb = __float2bfloat16(x - hf);
    h = __bfloat16_as_ushort(hb);
    l = __bfloat16_as_ushort(lb);
}
__device__ __forceinline__ float tf32_rna(float v) {
    uint32_t t;
    asm("cvt.rna.tf32.f32 %0, %1;" : "=r"(t) : "f"(v));
    return __uint_as_float(t);
}

// ---------------- mma.sync / ldmatrix / cp.async ----------------
#define LDSM4(r, addr) \
    asm volatile("ldmatrix.sync.aligned.m8n8.x4.shared.b16 {%0,%1,%2,%3}, [%4];" \
        : "=r"((r)[0]), "=r"((r)[1]), "=r"((r)[2]), "=r"((r)[3]) : "r"(addr))

#define MMA16816(c, a, b0, b1) \
    asm volatile("mma.sync.aligned.m16n8k16.row.col.f32.bf16.bf16.f32 " \
        "{%0,%1,%2,%3}, {%4,%5,%6,%7}, {%8,%9}, {%0,%1,%2,%3};" \
        : "+f"((c)[0]), "+f"((c)[1]), "+f"((c)[2]), "+f"((c)[3]) \
        : "r"((a)[0]), "r"((a)[1]), "r"((a)[2]), "r"((a)[3]), "r"(b0), "r"(b1))

// m16n8k8 tf32 (verified round 11)
#define MMA1688T(c, a, b0, b1) \
    asm volatile("mma.sync.aligned.m16n8k8.row.col.f32.tf32.tf32.f32 " \
        "{%0,%1,%2,%3}, {%4,%5,%6,%7}, {%8,%9}, {%0,%1,%2,%3};" \
        : "+f"((c)[0]), "+f"((c)[1]), "+f"((c)[2]), "+f"((c)[3]) \
        : "r"((a)[0]), "r"((a)[1]), "r"((a)[2]), "r"((a)[3]), "r"(b0), "r"(b1))

#define LDS32(r, addr) \
    asm volatile("ld.shared.b32 %0, [%1];" : "=r"(r) : "r"(addr))

#define CP16(sm, gm) \
    asm volatile("cp.async.cg.shared.global [%0], [%1], 16;" :: "r"(sm), "l"(gm))
#define CP_COMMIT() asm volatile("cp.async.commit_group;" ::: "memory")
#define CP_WAIT0()  asm volatile("cp.async.wait_group 0;" ::: "memory")

// ---------------------------------------------------------------------------
// Kernel W: convert W [96][1024] fp32 -> bf16 hi/lo
// ---------------------------------------------------------------------------
__global__ void __launch_bounds__(256) kernelW(
    const float* __restrict__ dw, const float* __restrict__ gw)
{
    int widx = blockIdx.x * 256 + threadIdx.x;   // < 24576
    int o  = widx >> 8;
    int kq = widx & 255;
    const float* src = (o < NDEC) ? (dw + (size_t)o * DIN) : (gw + (size_t)(o - NDEC) * DIN);
    float4 v = *(const float4*)(src + kq * 4);
    ushort4 hv, lv;
    split_bf16(v.x, hv.x, lv.x); split_bf16(v.y, hv.y, lv.y);
    split_bf16(v.z, hv.z, lv.z); split_bf16(v.w, hv.w, lv.w);
    *(ushort4*)(g_whi + (size_t)o * DIN + kq * 4) = hv;
    *(ushort4*)(g_wlo + (size_t)o * DIN + kq * 4) = lv;
}

// ---------------------------------------------------------------------------
// Kernel A (HMMA bf16 3-term, double-buffered — round-11 verbatim):
//   decisions = x @ W^T; epilogue -> tf32-rounded fp32 routed g_rt
// ---------------------------------------------------------------------------
#define AM    64
#define AKC   128
#define AST   136
#define ASTB  272
#define A_AL  (AM * AST)
#define A_BH  (2 * AM * AST)
#define BUF_SHORTS (2 * AM * AST + 2 * NOUT * AST)
#define BUF_BYTES  (BUF_SHORTS * 2)
#define SMEM_A_BYTES (2 * BUF_BYTES)
#define DEC_S 97

__global__ void __launch_bounds__(256, 1) kernelA(
    const float* __restrict__ x,
    const float* __restrict__ db,
    const float* __restrict__ ntl,
    const float* __restrict__ gb,
    const int*   __restrict__ pidx,
    const float* __restrict__ pdir)
{
    extern __shared__ __align__(16) unsigned short sa[];
    __shared__ float s_invt[NDEC];
    __shared__ float s_bias[NDEC];
    __shared__ float s_gb[NT];
    __shared__ int   s_pi[NL * 3];
    __shared__ float s_pd[NL * 3];

    const int tid  = threadIdx.x;
    const int lane = tid & 31;
    const int wid  = tid >> 5;
    const int wr   = wid & 3;
    const int wc   = wid >> 2;
    const int tok0 = blockIdx.x * AM;
    const uint32_t smbase = smem_u32(sa);

    if (tid < NDEC) {
        float t  = ntl[tid] + 0.5413f;
        float sp = (t > 20.f) ? t : log1pf(__expf(t));
        s_invt[tid] = 1.0f / sp;
        s_bias[tid] = db[tid];
    } else if (tid < NDEC + NT) {
        s_gb[tid - NDEC] = gb[tid - NDEC];
    } else if (tid < NDEC + NT + NL * 3) {
        int i = tid - NDEC - NT;
        s_pi[i] = pidx[i];
        s_pd[i] = pdir[i];
    }

    const int xr  = tid >> 5;
    const int xkq = tid & 31;
    const int wrr = tid >> 4;
    const int wq  = tid & 15;

    float acc[6][4];
    #pragma unroll
    for (int n = 0; n < 6; n++)
        #pragma unroll
        for (int e = 0; e < 4; e++) acc[n][e] = 0.f;

    const uint32_t aoff = (wr * 16 + (lane & 15)) * ASTB + ((lane >> 4) & 1) * 16;
    const uint32_t boff = (wc * 48 + (lane & 7) + ((lane & 16) ? 8 : 0)) * ASTB + ((lane & 8) ? 16 : 0);

    float4 xv[8];
    #pragma unroll
    for (int it = 0; it < 8; it++) {
        int r = it * 8 + xr;
        xv[it] = *(const float4*)(x + (size_t)(tok0 + r) * DIN + xkq * 4);
    }
    #pragma unroll
    for (int it = 0; it < 6; it++) {
        int r = it * 16 + wrr;
        uint32_t dsth = smbase + (A_BH + r * AST + wq * 8) * 2;
        CP16(dsth, g_whi + (size_t)r * DIN + wq * 8);
        CP16(dsth + (NOUT * AST) * 2, g_wlo + (size_t)r * DIN + wq * 8);
    }
    CP_COMMIT();

    for (int kc = 0; kc < 8; kc++) {
        const int b = kc & 1;
        unsigned short* Ah = sa + b * BUF_SHORTS;
        unsigned short* Al = Ah + A_AL;
        const uint32_t sb = smbase + b * BUF_BYTES;

        float4 xn[8];
        if (kc < 7) {
            #pragma unroll
            for (int it = 0; it < 8; it++) {
                int r = it * 8 + xr;
                xn[it] = *(const float4*)(x + (size_t)(tok0 + r) * DIN + (kc + 1) * AKC + xkq * 4);
            }
        }

        #pragma unroll
        for (int it = 0; it < 8; it++) {
            int r = it * 8 + xr;
            ushort4 hv, lv;
            split_bf16(xv[it].x, hv.x, lv.x); split_bf16(xv[it].y, hv.y, lv.y);
            split_bf16(xv[it].z, hv.z, lv.z); split_bf16(xv[it].w, hv.w, lv.w);
            *(ushort4*)(Ah + r * AST + xkq * 4) = hv;
            *(ushort4*)(Al + r * AST + xkq * 4) = lv;
        }
        CP_WAIT0();
        __syncthreads();

        if (kc < 7) {
            const uint32_t so = smbase + (1 - b) * BUF_BYTES;
            #pragma unroll
            for (int it = 0; it < 6; it++) {
                int r = it * 16 + wrr;
                uint32_t dsth = so + (A_BH + r * AST + wq * 8) * 2;
                CP16(dsth, g_whi + (size_t)r * DIN + (kc + 1) * AKC + wq * 8);
                CP16(dsth + (NOUT * AST) * 2, g_wlo + (size_t)r * DIN + (kc + 1) * AKC + wq * 8);
            }
            CP_COMMIT();
        }

        const uint32_t aH0 = sb + aoff;
        const uint32_t aL0 = aH0 + AM * ASTB;
        const uint32_t bH0 = sb + A_BH * 2 + boff;
        const uint32_t bL0 = bH0 + NOUT * ASTB;
        #pragma unroll
        for (int ks = 0; ks < 8; ks++) {
            uint32_t ah[4], al[4];
            LDSM4(ah, aH0 + ks * 32);
            LDSM4(al, aL0 + ks * 32);
            #pragma unroll
            for (int g = 0; g < 3; g++) {
                uint32_t bh[4], bl[4];
                LDSM4(bh, bH0 + g * 16 * ASTB + ks * 32);
                LDSM4(bl, bL0 + g * 16 * ASTB + ks * 32);
                MMA16816(acc[2 * g],     ah, bh[0], bh[1]);
                MMA16816(acc[2 * g + 1], ah, bh[2], bh[3]);
                MMA16816(acc[2 * g],     ah, bl[0], bl[1]);
                MMA16816(acc[2 * g + 1], ah, bl[2], bl[3]);
                MMA16816(acc[2 * g],     al, bh[0], bh[1]);
                MMA16816(acc[2 * g + 1], al, bh[2], bh[3]);
            }
        }
        __syncthreads();

        if (kc < 7) {
            #pragma unroll
            for (int it = 0; it < 8; it++) xv[it] = xn[it];
        }
    }

    float* Dec = (float*)sa;
    const int trow = lane >> 2;
    const int tcol = (lane & 3) * 2;
    #pragma unroll
    for (int nt = 0; nt < 6; nt++) {
        int col = wc * 48 + nt * 8 + tcol;
        Dec[(wr * 16 + trow) * DEC_S + col]         = acc[nt][0];
        Dec[(wr * 16 + trow) * DEC_S + col + 1]     = acc[nt][1];
        Dec[(wr * 16 + trow + 8) * DEC_S + col]     = acc[nt][2];
        Dec[(wr * 16 + trow + 8) * DEC_S + col + 1] = acc[nt][3];
    }
    __syncthreads();

    if (tid < AM) {
        const int token = tok0 + tid;
        const float* d = Dec + tid * DEC_S;

        float g[NT];
        float m = -1e30f;
        #pragma unroll
        for (int t = 0; t < NT; t++) { g[t] = d[NDEC + t] + s_gb[t]; m = fmaxf(m, g[t]); }
        float sum = 0.f;
        #pragma unroll
        for (int t = 0; t < NT; t++) { g[t] = __expf(g[t] - m); sum += g[t]; }
        const float inv = 1.0f / sum;

        float* rt = g_rt + (size_t)token * NOUT;

        #pragma unroll
        for (int t = 0; t < NT; t++) {
            const float wgt = g[t] * inv;
            float sg[NI];
            #pragma unroll
            for (int n = 0; n < NI; n++) {
                float z = (d[t * NI + n] + s_bias[t * NI + n]) * s_invt[t * NI + n];
                sg[n] = 1.0f / (1.0f + __expf(-z));
            }
            #pragma unroll
            for (int l = 0; l < NL; l++) {
                float p = wgt;
                #pragma unroll
                for (int dd = 0; dd < 3; dd++) {
                    float sv  = sg[s_pi[l * 3 + dd]];
                    float dir = s_pd[l * 3 + dd];
                    p *= dir * sv + (1.f - dir) * (1.f - sv);
                }
                rt[t * NL + l] = tf32_rna(p);
            }
        }
    }
}

// ---------------------------------------------------------------------------
// Kernel B v8 (TF32 m16n8k8; same CTA tile as round-15, finer warps):
//   out[h, 128 tok, 256 d] = rt[128,96] @ lo[h][96, 256-slice], 2 iters BN=128
//   512 threads, 16 warps = 4 tok-groups(32) x 4 d-groups(32); warp tile 32x32
//   acc 32 regs/thread -> ~80 regs -> 2 CTAs/SM = 32 warps/SM (was 16)
// ---------------------------------------------------------------------------
#define BM 128
#define BN 128
#define ASTRIDE 100
#define BSTRIDE 136
#define AS4 (ASTRIDE * 4)
#define BS4 (BSTRIDE * 4)
#define AB_BYTES (BM * AS4)       // 51200
#define BB_BYTES (NOUT * BS4)     // 52224
#define SMEM_B_BYTES (AB_BYTES + BB_BYTES + 16)

__global__ void __launch_bounds__(512, 2) kernelB(
    const float* __restrict__ lo, float* __restrict__ out)
{
    extern __shared__ __align__(16) unsigned char shb[];
    const uint32_t abase = smem_u32(shb);
    const uint32_t bbase = abase + AB_BYTES;

    const int tid  = threadIdx.x;
    const int lane = tid & 31;
    const int wid  = tid >> 5;
    const int wr   = wid & 3;      // 4 token groups of 32
    const int wc   = wid >> 2;     // 4 d groups of 32
    const int tok0 = blockIdx.x * BM;
    const int dsp0 = blockIdx.y * 256;
    const int h    = blockIdx.z;

    // ---- stage A once: 128 rows x 96 fp32 (3072 chunks / 512 thr) ----
    #pragma unroll
    for (int p = 0; p < 6; p++) {
        int i = p * 512 + tid;
        int r = i / 24, q = i - r * 24;
        CP16(abase + r * AS4 + q * 16,
             (const char*)g_rt + (size_t)(tok0 + r) * 384 + q * 16);
    }
    // ---- stage B tile 0: 96 rows x 128 fp32 (3072 chunks / 512 thr) ----
    #pragma unroll
    for (int p = 0; p < 6; p++) {
        int i = p * 512 + tid;
        int r = i >> 5, q = i & 31;
        CP16(bbase + r * BS4 + q * 16,
             (const char*)lo + ((size_t)(h * NOUT + r) * DOUTD + dsp0 + q * 4) * 4);
    }
    CP_COMMIT();

    const int gid = lane >> 2;     // 0..7
    const int tig = lane & 3;      // 0..3
    // A: row = wr*32 + mt*16 + gid (+8 for a1/a3), col(k) = s*8 + tig (+4 for a2/a3)
    const uint32_t a_lane = ((wr * 32 + gid) * ASTRIDE + tig) * 4;
    // B: row(k) = s*8 + tig (+4 for b1), col(n) = wc*32 + nt*8 + gid
    const uint32_t b_lane = (tig * BSTRIDE + wc * 32 + gid) * 4;

    for (int it = 0; it < 2; it++) {
        CP_WAIT0();
        __syncthreads();
        const int d0 = dsp0 + it * BN;

        float acc[2][4][4];
        #pragma unroll
        for (int m = 0; m < 2; m++)
            #pragma unroll
            for (int n = 0; n < 4; n++)
                #pragma unroll
                for (int e = 0; e < 4; e++) acc[m][n][e] = 0.f;

        #pragma unroll
        for (int s = 0; s < 12; s++) {           // k-steps of 8
            uint32_t a[2][4];
            const uint32_t ab = abase + a_lane + s * 32;
            #pragma unroll
            for (int mt = 0; mt < 2; mt++) {
                const uint32_t am = ab + mt * 16 * AS4;
                LDS32(a[mt][0], am);
                LDS32(a[mt][1], am + 8 * AS4);
                LDS32(a[mt][2], am + 16);
                LDS32(a[mt][3], am + 8 * AS4 + 16);
            }
            uint32_t b[4][2];
            const uint32_t bbs = bbase + b_lane + s * 8 * BS4;
            #pragma unroll
            for (int nt = 0; nt < 4; nt++) {
                LDS32(b[nt][0], bbs + nt * 32);
                LDS32(b[nt][1], bbs + nt * 32 + 4 * BS4);
            }
            #pragma unroll
            for (int mt = 0; mt < 2; mt++)
                #pragma unroll
                for (int nt = 0; nt < 4; nt++)
                    MMA1688T(acc[mt][nt], a[mt], b[nt][0], b[nt][1]);
        }

        __syncthreads();   // all B reads done before restage
        if (it < 1) {
            const int dn = dsp0 + BN;
            #pragma unroll
            for (int p = 0; p < 6; p++) {
                int i = p * 512 + tid;
                int r = i >> 5, q = i & 31;
                CP16(bbase + r * BS4 + q * 16,
                     (const char*)lo + ((size_t)(h * NOUT + r) * DOUTD + dn + q * 4) * 4);
            }
            CP_COMMIT();
        }

        // store tile (overlaps with cp.async flight)
        #pragma unroll
        for (int mt = 0; mt < 2; mt++) {
            int row = tok0 + wr * 32 + mt * 16 + gid;
            float* ob0 = out + ((size_t)h * NTOK + row) * DOUTD + d0 + wc * 32 + tig * 2;
            float* ob1 = ob0 + 8 * DOUTD;
            #pragma unroll
            for (int nt = 0; nt < 4; nt++) {
                *(float2*)(ob0 + nt * 8) = make_float2(acc[mt][nt][0], acc[mt][nt][1]);
                *(float2*)(ob1 + nt * 8) = make_float2(acc[mt][nt][2], acc[mt][nt][3]);
            }
        }
    }
}

// ---------------------------------------------------------------------------
extern "C" void kernel_launch(void* const* d_in, const int* in_sizes, int n_in,
                              void* d_out, int out_size) {
    const float* x    = (const float*)d_in[0];
    const float* dw   = (const float*)d_in[1];
    const float* db   = (const float*)d_in[2];
    const float* ntl  = (const float*)d_in[3];
    const float* gw   = (const float*)d_in[4];
    const float* gb   = (const float*)d_in[5];
    const float* lo   = (const float*)d_in[6];
    const int*   pidx = (const int*)d_in[7];
    const float* pdir = (const float*)d_in[8];
    float* out = (float*)d_out;

    cudaFuncSetAttribute(kernelA, cudaFuncAttributeMaxDynamicSharedMemorySize, SMEM_A_BYTES);
    cudaFuncSetAttribute(kernelB, cudaFuncAttributeMaxDynamicSharedMemorySize, SMEM_B_BYTES);

    kernelW<<<96, 256>>>(dw, gw);
    kernelA<<<NTOK / AM, 256, SMEM_A_BYTES>>>(x, db, ntl, gb, pidx, pdir);

    dim3 gridB(NTOK / BM, DOUTD / 256, NHEADS);
    kernelB<<<gridB, 512, SMEM_B_BYTES>>>(lo, out);
}

// round 17
// speedup vs baseline: 1.1645x; 1.1645x over previous
#include <cuda_runtime.h>
#include <cuda_bf16.h>
#include <math.h>
#include <stdint.h>

// Problem constants
#define NTOK   8192
#define DIN    1024
#define NT     12
#define NI     7
#define NL     8
#define NDEC   84
#define NOUT   96
#define DOUTD  1024
#define NHEADS 3

// ---------------- scratch (device globals) ----------------
__device__ __align__(16) float g_rt[NTOK * NOUT];            // routed, tf32-rounded fp32 [tok][96]
__device__ __align__(16) unsigned short g_whi[NOUT * DIN];   // W hi bf16 [96][1024]
__device__ __align__(16) unsigned short g_wlo[NOUT * DIN];   // W lo

__device__ __forceinline__ uint32_t smem_u32(const void* p) {
    uint32_t a;
    asm("{ .reg .u64 t; cvta.to.shared.u64 t, %1; cvt.u32.u64 %0, t; }" : "=r"(a) : "l"(p));
    return a;
}
__device__ __forceinline__ void split_bf16(float x, unsigned short &h, unsigned short &l) {
    __nv_bfloat16 hb = __float2bfloat16(x);
    float hf = __bfloat162float(hb);
    __nv_bfloat16 lb = __float2bfloat16(x - hf);
    h = __bfloat16_as_ushort(hb);
    l = __bfloat16_as_ushort(lb);
}
__device__ __forceinline__ float tf32_rna(float v) {
    uint32_t t;
    asm("cvt.rna.tf32.f32 %0, %1;" : "=r"(t) : "f"(v));
    return __uint_as_float(t);
}

// ---------------- mma.sync / ldmatrix / cp.async ----------------
#define LDSM4(r, addr) \
    asm volatile("ldmatrix.sync.aligned.m8n8.x4.shared.b16 {%0,%1,%2,%3}, [%4];" \
        : "=r"((r)[0]), "=r"((r)[1]), "=r"((r)[2]), "=r"((r)[3]) : "r"(addr))

#define MMA16816(c, a, b0, b1) \
    asm volatile("mma.sync.aligned.m16n8k16.row.col.f32.bf16.bf16.f32 " \
        "{%0,%1,%2,%3}, {%4,%5,%6,%7}, {%8,%9}, {%0,%1,%2,%3};" \
        : "+f"((c)[0]), "+f"((c)[1]), "+f"((c)[2]), "+f"((c)[3]) \
        : "r"((a)[0]), "r"((a)[1]), "r"((a)[2]), "r"((a)[3]), "r"(b0), "r"(b1))

// m16n8k8 tf32 (verified round 11)
#define MMA1688T(c, a, b0, b1) \
    asm volatile("mma.sync.aligned.m16n8k8.row.col.f32.tf32.tf32.f32 " \
        "{%0,%1,%2,%3}, {%4,%5,%6,%7}, {%8,%9}, {%0,%1,%2,%3};" \
        : "+f"((c)[0]), "+f"((c)[1]), "+f"((c)[2]), "+f"((c)[3]) \
        : "r"((a)[0]), "r"((a)[1]), "r"((a)[2]), "r"((a)[3]), "r"(b0), "r"(b1))

#define LDS32(r, addr) \
    asm volatile("ld.shared.b32 %0, [%1];" : "=r"(r) : "r"(addr))

#define CP16(sm, gm) \
    asm volatile("cp.async.cg.shared.global [%0], [%1], 16;" :: "r"(sm), "l"(gm))
#define CP_COMMIT() asm volatile("cp.async.commit_group;" ::: "memory")
#define CP_WAIT0()  asm volatile("cp.async.wait_group 0;" ::: "memory")

// ---------------------------------------------------------------------------
// Kernel W: convert W [96][1024] fp32 -> bf16 hi/lo
// ---------------------------------------------------------------------------
__global__ void __launch_bounds__(256) kernelW(
    const float* __restrict__ dw, const float* __restrict__ gw)
{
    int widx = blockIdx.x * 256 + threadIdx.x;   // < 24576
    int o  = widx >> 8;
    int kq = widx & 255;
    const float* src = (o < NDEC) ? (dw + (size_t)o * DIN) : (gw + (size_t)(o - NDEC) * DIN);
    float4 v = *(const float4*)(src + kq * 4);
    ushort4 hv, lv;
    split_bf16(v.x, hv.x, lv.x); split_bf16(v.y, hv.y, lv.y);
    split_bf16(v.z, hv.z, lv.z); split_bf16(v.w, hv.w, lv.w);
    *(ushort4*)(g_whi + (size_t)o * DIN + kq * 4) = hv;
    *(ushort4*)(g_wlo + (size_t)o * DIN + kq * 4) = lv;
}

// ---------------------------------------------------------------------------
// Kernel A (HMMA bf16 3-term, double-buffered; round-11 GEMM core,
//   epilogue parallelized over all 256 threads):
//   decisions = x @ W^T; epilogue -> tf32-rounded fp32 routed g_rt
// ---------------------------------------------------------------------------
#define AM    64
#define AKC   128
#define AST   136
#define ASTB  272
#define A_AL  (AM * AST)
#define A_BH  (2 * AM * AST)
#define BUF_SHORTS (2 * AM * AST + 2 * NOUT * AST)
#define BUF_BYTES  (BUF_SHORTS * 2)
#define SMEM_A_BYTES (2 * BUF_BYTES)
#define DEC_S 97
#define SW_S  13

__global__ void __launch_bounds__(256, 1) kernelA(
    const float* __restrict__ x,
    const float* __restrict__ db,
    const float* __restrict__ ntl,
    const float* __restrict__ gb,
    const int*   __restrict__ pidx,
    const float* __restrict__ pdir)
{
    extern __shared__ __align__(16) unsigned short sa[];
    __shared__ float s_invt[NDEC];
    __shared__ float s_bias[NDEC];
    __shared__ float s_gb[NT];
    __shared__ int   s_pi[NL * 3];
    __shared__ float s_pd[NL * 3];

    const int tid  = threadIdx.x;
    const int lane = tid & 31;
    const int wid  = tid >> 5;
    const int wr   = wid & 3;
    const int wc   = wid >> 2;
    const int tok0 = blockIdx.x * AM;
    const uint32_t smbase = smem_u32(sa);

    if (tid < NDEC) {
        float t  = ntl[tid] + 0.5413f;
        float sp = (t > 20.f) ? t : log1pf(__expf(t));
        s_invt[tid] = 1.0f / sp;
        s_bias[tid] = db[tid];
    } else if (tid < NDEC + NT) {
        s_gb[tid - NDEC] = gb[tid - NDEC];
    } else if (tid < NDEC + NT + NL * 3) {
        int i = tid - NDEC - NT;
        s_pi[i] = pidx[i];
        s_pd[i] = pdir[i];
    }

    const int xr  = tid >> 5;
    const int xkq = tid & 31;
    const int wrr = tid >> 4;
    const int wq  = tid & 15;

    float acc[6][4];
    #pragma unroll
    for (int n = 0; n < 6; n++)
        #pragma unroll
        for (int e = 0; e < 4; e++) acc[n][e] = 0.f;

    const uint32_t aoff = (wr * 16 + (lane & 15)) * ASTB + ((lane >> 4) & 1) * 16;
    const uint32_t boff = (wc * 48 + (lane & 7) + ((lane & 16) ? 8 : 0)) * ASTB + ((lane & 8) ? 16 : 0);

    float4 xv[8];
    #pragma unroll
    for (int it = 0; it < 8; it++) {
        int r = it * 8 + xr;
        xv[it] = *(const float4*)(x + (size_t)(tok0 + r) * DIN + xkq * 4);
    }
    #pragma unroll
    for (int it = 0; it < 6; it++) {
        int r = it * 16 + wrr;
        uint32_t dsth = smbase + (A_BH + r * AST + wq * 8) * 2;
        CP16(dsth, g_whi + (size_t)r * DIN + wq * 8);
        CP16(dsth + (NOUT * AST) * 2, g_wlo + (size_t)r * DIN + wq * 8);
    }
    CP_COMMIT();

    for (int kc = 0; kc < 8; kc++) {
        const int b = kc & 1;
        unsigned short* Ah = sa + b * BUF_SHORTS;
        unsigned short* Al = Ah + A_AL;
        const uint32_t sb = smbase + b * BUF_BYTES;

        float4 xn[8];
        if (kc < 7) {
            #pragma unroll
            for (int it = 0; it < 8; it++) {
                int r = it * 8 + xr;
                xn[it] = *(const float4*)(x + (size_t)(tok0 + r) * DIN + (kc + 1) * AKC + xkq * 4);
            }
        }

        #pragma unroll
        for (int it = 0; it < 8; it++) {
            int r = it * 8 + xr;
            ushort4 hv, lv;
            split_bf16(xv[it].x, hv.x, lv.x); split_bf16(xv[it].y, hv.y, lv.y);
            split_bf16(xv[it].z, hv.z, lv.z); split_bf16(xv[it].w, hv.w, lv.w);
            *(ushort4*)(Ah + r * AST + xkq * 4) = hv;
            *(ushort4*)(Al + r * AST + xkq * 4) = lv;
        }
        CP_WAIT0();
        __syncthreads();

        if (kc < 7) {
            const uint32_t so = smbase + (1 - b) * BUF_BYTES;
            #pragma unroll
            for (int it = 0; it < 6; it++) {
                int r = it * 16 + wrr;
                uint32_t dsth = so + (A_BH + r * AST + wq * 8) * 2;
                CP16(dsth, g_whi + (size_t)r * DIN + (kc + 1) * AKC + wq * 8);
                CP16(dsth + (NOUT * AST) * 2, g_wlo + (size_t)r * DIN + (kc + 1) * AKC + wq * 8);
            }
            CP_COMMIT();
        }

        const uint32_t aH0 = sb + aoff;
        const uint32_t aL0 = aH0 + AM * ASTB;
        const uint32_t bH0 = sb + A_BH * 2 + boff;
        const uint32_t bL0 = bH0 + NOUT * ASTB;
        #pragma unroll
        for (int ks = 0; ks < 8; ks++) {
            uint32_t ah[4], al[4];
            LDSM4(ah, aH0 + ks * 32);
            LDSM4(al, aL0 + ks * 32);
            #pragma unroll
            for (int g = 0; g < 3; g++) {
                uint32_t bh[4], bl[4];
                LDSM4(bh, bH0 + g * 16 * ASTB + ks * 32);
                LDSM4(bl, bL0 + g * 16 * ASTB + ks * 32);
                MMA16816(acc[2 * g],     ah, bh[0], bh[1]);
                MMA16816(acc[2 * g + 1], ah, bh[2], bh[3]);
                MMA16816(acc[2 * g],     ah, bl[0], bl[1]);
                MMA16816(acc[2 * g + 1], ah, bl[2], bl[3]);
                MMA16816(acc[2 * g],     al, bh[0], bh[1]);
                MMA16816(acc[2 * g + 1], al, bh[2], bh[3]);
            }
        }
        __syncthreads();

        if (kc < 7) {
            #pragma unroll
            for (int it = 0; it < 8; it++) xv[it] = xn[it];
        }
    }

    // ---- epilogue ----
    float* Dec = (float*)sa;                       // [64][97]
    float* SW  = (float*)sa + AM * DEC_S;          // [64][13] gate weights
    const int trow = lane >> 2;
    const int tcol = (lane & 3) * 2;
    #pragma unroll
    for (int nt = 0; nt < 6; nt++) {
        int col = wc * 48 + nt * 8 + tcol;
        Dec[(wr * 16 + trow) * DEC_S + col]         = acc[nt][0];
        Dec[(wr * 16 + trow) * DEC_S + col + 1]     = acc[nt][1];
        Dec[(wr * 16 + trow + 8) * DEC_S + col]     = acc[nt][2];
        Dec[(wr * 16 + trow + 8) * DEC_S + col + 1] = acc[nt][3];
    }
    __syncthreads();

    // phase 1: gate softmax per token (64 threads)
    if (tid < AM) {
        const float* d = Dec + tid * DEC_S;
        float g[NT];
        float m = -1e30f;
        #pragma unroll
        for (int t = 0; t < NT; t++) { g[t] = d[NDEC + t] + s_gb[t]; m = fmaxf(m, g[t]); }
        float sum = 0.f;
        #pragma unroll
        for (int t = 0; t < NT; t++) { g[t] = __expf(g[t] - m); sum += g[t]; }
        const float inv = 1.0f / sum;
        #pragma unroll
        for (int t = 0; t < NT; t++) SW[tid * SW_S + t] = g[t] * inv;
    }
    __syncthreads();

    // phase 2: trees spread over all 256 threads (3 trees per thread)
    {
        const int tok = tid & 63;
        const int tg  = tid >> 6;          // 0..3
        const float* d = Dec + tok * DEC_S;
        float* rt = g_rt + (size_t)(tok0 + tok) * NOUT;

        #pragma unroll
        for (int tt = 0; tt < 3; tt++) {
            const int t = tg * 3 + tt;
            const float wgt = SW[tok * SW_S + t];
            float sg[NI];
            #pragma unroll
            for (int n = 0; n < NI; n++) {
                float z = (d[t * NI + n] + s_bias[t * NI + n]) * s_invt[t * NI + n];
                sg[n] = 1.0f / (1.0f + __expf(-z));
            }
            #pragma unroll
            for (int l = 0; l < NL; l++) {
                float p = wgt;
                #pragma unroll
                for (int dd = 0; dd < 3; dd++) {
                    float sv  = sg[s_pi[l * 3 + dd]];
                    float dir = s_pd[l * 3 + dd];
                    p *= dir * sv + (1.f - dir) * (1.f - sv);
                }
                rt[t * NL + l] = tf32_rna(p);
            }
        }
    }
}

// ---------------------------------------------------------------------------
// Kernel B (TF32 m16n8k8, round-15 verbatim — measured 48.7us x3):
//   out[h, 128 tok, 256 d] = rt[128,96] @ lo[h][96, 256-slice], 2 iters BN=128
// ---------------------------------------------------------------------------
#define BM 128
#define BN 128
#define ASTRIDE 100
#define BSTRIDE 136
#define AS4 (ASTRIDE * 4)
#define BS4 (BSTRIDE * 4)
#define AB_BYTES (BM * AS4)       // 51200
#define BB_BYTES (NOUT * BS4)     // 52224
#define SMEM_B_BYTES (AB_BYTES + BB_BYTES + 16)

__global__ void __launch_bounds__(256, 2) kernelB(
    const float* __restrict__ lo, float* __restrict__ out)
{
    extern __shared__ __align__(16) unsigned char shb[];
    const uint32_t abase = smem_u32(shb);
    const uint32_t bbase = abase + AB_BYTES;

    const int tid  = threadIdx.x;
    const int lane = tid & 31;
    const int wid  = tid >> 5;
    const int wr   = wid & 1;      // 2 token groups of 64
    const int wc   = wid >> 1;     // 4 d groups of 32
    const int tok0 = blockIdx.x * BM;
    const int dsp0 = blockIdx.y * 256;
    const int h    = blockIdx.z;

    #pragma unroll
    for (int p = 0; p < 12; p++) {
        int i = p * 256 + tid;
        int r = i / 24, q = i - r * 24;
        CP16(abase + r * AS4 + q * 16,
             (const char*)g_rt + (size_t)(tok0 + r) * 384 + q * 16);
    }
    #pragma unroll
    for (int p = 0; p < 12; p++) {
        int i = p * 256 + tid;
        int r = i >> 5, q = i & 31;
        CP16(bbase + r * BS4 + q * 16,
             (const char*)lo + ((size_t)(h * NOUT + r) * DOUTD + dsp0 + q * 4) * 4);
    }
    CP_COMMIT();

    const int gid = lane >> 2;
    const int tig = lane & 3;
    const uint32_t a_lane = ((wr * 64 + gid) * ASTRIDE + tig) * 4;
    const uint32_t b_lane = (tig * BSTRIDE + wc * 32 + gid) * 4;

    for (int it = 0; it < 2; it++) {
        CP_WAIT0();
        __syncthreads();
        const int d0 = dsp0 + it * BN;

        float acc[4][4][4];
        #pragma unroll
        for (int m = 0; m < 4; m++)
            #pragma unroll
            for (int n = 0; n < 4; n++)
                #pragma unroll
                for (int e = 0; e < 4; e++) acc[m][n][e] = 0.f;

        #pragma unroll
        for (int s = 0; s < 12; s++) {
            uint32_t a[4][4];
            const uint32_t ab = abase + a_lane + s * 32;
            #pragma unroll
            for (int mt = 0; mt < 4; mt++) {
                const uint32_t am = ab + mt * 16 * AS4;
                LDS32(a[mt][0], am);
                LDS32(a[mt][1], am + 8 * AS4);
                LDS32(a[mt][2], am + 16);
                LDS32(a[mt][3], am + 8 * AS4 + 16);
            }
            uint32_t b[4][2];
            const uint32_t bbs = bbase + b_lane + s * 8 * BS4;
            #pragma unroll
            for (int nt = 0; nt < 4; nt++) {
                LDS32(b[nt][0], bbs + nt * 32);
                LDS32(b[nt][1], bbs + nt * 32 + 4 * BS4);
            }
            #pragma unroll
            for (int mt = 0; mt < 4; mt++)
                #pragma unroll
                for (int nt = 0; nt < 4; nt++)
                    MMA1688T(acc[mt][nt], a[mt], b[nt][0], b[nt][1]);
        }

        __syncthreads();
        if (it < 1) {
            const int dn = dsp0 + BN;
            #pragma unroll
            for (int p = 0; p < 12; p++) {
                int i = p * 256 + tid;
                int r = i >> 5, q = i & 31;
                CP16(bbase + r * BS4 + q * 16,
                     (const char*)lo + ((size_t)(h * NOUT + r) * DOUTD + dn + q * 4) * 4);
            }
            CP_COMMIT();
        }

        #pragma unroll
        for (int mt = 0; mt < 4; mt++) {
            int row = tok0 + wr * 64 + mt * 16 + gid;
            float* ob0 = out + ((size_t)h * NTOK + row) * DOUTD + d0 + wc * 32 + tig * 2;
            float* ob1 = ob0 + 8 * DOUTD;
            #pragma unroll
            for (int nt = 0; nt < 4; nt++) {
                *(float2*)(ob0 + nt * 8) = make_float2(acc[mt][nt][0], acc[mt][nt][1]);
                *(float2*)(ob1 + nt * 8) = make_float2(acc[mt][nt][2], acc[mt][nt][3]);
            }
        }
    }
}

// ---------------------------------------------------------------------------
extern "C" void kernel_launch(void* const* d_in, const int* in_sizes, int n_in,
                              void* d_out, int out_size) {
    const float* x    = (const float*)d_in[0];
    const float* dw   = (const float*)d_in[1];
    const float* db   = (const float*)d_in[2];
    const float* ntl  = (const float*)d_in[3];
    const float* gw   = (const float*)d_in[4];
    const float* gb   = (const float*)d_in[5];
    const float* lo   = (const float*)d_in[6];
    const int*   pidx = (const int*)d_in[7];
    const float* pdir = (const float*)d_in[8];
    float* out = (float*)d_out;

    cudaFuncSetAttribute(kernelA, cudaFuncAttributeMaxDynamicSharedMemorySize, SMEM_A_BYTES);
    cudaFuncSetAttribute(kernelB, cudaFuncAttributeMaxDynamicSharedMemorySize, SMEM_B_BYTES);

    kernelW<<<96, 256>>>(dw, gw);
    kernelA<<<NTOK / AM, 256, SMEM_A_BYTES>>>(x, db, ntl, gb, pidx, pdir);

    dim3 gridB(NTOK / BM, DOUTD / 256, NHEADS);
    kernelB<<<gridB, 256, SMEM_B_BYTES>>>(lo, out);
}